// round 1
// baseline (speedup 1.0000x reference)
#include <cuda_runtime.h>
#include <cuda_bf16.h>
#include <math.h>

// Problem constants (FMoE_644245095184): E=8 experts, D=1024, H=2048, T=2048, top_k=2
#define T_TOK  2048
#define DMODEL 1024
#define HID    2048
#define NEXP   8

// ---- Scratch (device globals: allocation-free, zero-init at module load) ----
__device__ float g_hidden[(size_t)NEXP * T_TOK * HID];   // per-expert gelu(h) rows, [e][row][H]  (~134 MB)
__device__ float g_ys[(size_t)T_TOK * 2 * DMODEL];       // per-assignment weighted expert output (~16.8 MB)
__device__ float g_gatew[T_TOK * 2];                     // softmaxed gate weight per assignment
__device__ int   g_assign[NEXP * T_TOK];                 // per-expert list of assignment ids (token*2+slot)
__device__ int   g_count[NEXP];                          // rows per expert

__global__ void zero_counts_kernel() {
    if (threadIdx.x < NEXP) g_count[threadIdx.x] = 0;
}

// ---- Gate: fp32 logits, top-2, softmax. One warp per token. ----
__global__ void gate_kernel(const float* __restrict__ x, const float* __restrict__ Wg,
                            const float* __restrict__ bg, float* __restrict__ out_tail,
                            int write_idx) {
    int warp = (blockIdx.x * blockDim.x + threadIdx.x) >> 5;
    int lane = threadIdx.x & 31;
    if (warp >= T_TOK) return;
    const float* xr = x + (size_t)warp * DMODEL;
    float acc[NEXP];
#pragma unroll
    for (int e = 0; e < NEXP; e++) acc[e] = 0.f;
    for (int k = lane; k < DMODEL; k += 32) {
        float xv = xr[k];
        const float* wr = Wg + k * NEXP;
#pragma unroll
        for (int e = 0; e < NEXP; e++) acc[e] += xv * wr[e];
    }
#pragma unroll
    for (int e = 0; e < NEXP; e++) {
#pragma unroll
        for (int off = 16; off > 0; off >>= 1)
            acc[e] += __shfl_down_sync(0xffffffffu, acc[e], off);
    }
    if (lane == 0) {
#pragma unroll
        for (int e = 0; e < NEXP; e++) acc[e] += bg[e];
        // top-1 (first occurrence on ties, matching lax.top_k lower-index-first)
        int i0 = 0; float v0 = acc[0];
#pragma unroll
        for (int e = 1; e < NEXP; e++) if (acc[e] > v0) { v0 = acc[e]; i0 = e; }
        int i1 = -1; float v1 = -INFINITY;
#pragma unroll
        for (int e = 0; e < NEXP; e++) if (e != i0 && acc[e] > v1) { v1 = acc[e]; i1 = e; }
        // softmax over [v0, v1] (v0 >= v1)
        float ex = expf(v1 - v0);
        float inv = 1.f / (1.f + ex);
        g_gatew[2 * warp]     = inv;
        g_gatew[2 * warp + 1] = ex * inv;
        int p0 = atomicAdd(&g_count[i0], 1);
        g_assign[i0 * T_TOK + p0] = 2 * warp;
        int p1 = atomicAdd(&g_count[i1], 1);
        g_assign[i1 * T_TOK + p1] = 2 * warp + 1;
        if (write_idx) {
            out_tail[2 * warp]     = (float)i0;
            out_tail[2 * warp + 1] = (float)i1;
        }
    }
}

__device__ __forceinline__ float gelu_tanh(float v) {
    float t = tanhf(0.7978845608028654f * (v + 0.044715f * v * v * v));
    return 0.5f * v * (1.f + t);
}

// ---- FFN GEMM 1: hidden = gelu(gather(x) @ W1[e] + b1[e]) ----
// 128x128 tile, BK=8, 256 threads, 8x8 per thread.
__global__ __launch_bounds__(256, 2)
void ffn1_kernel(const float* __restrict__ x, const float* __restrict__ W1,
                 const float* __restrict__ b1) {
    int e = blockIdx.z;
    int n_e = g_count[e];
    int m0 = blockIdx.y * 128;
    if (m0 >= n_e) return;
    int n0 = blockIdx.x * 128;

    __shared__ float As[8][128];
    __shared__ float Bs[8][128];

    const float* B = W1 + (size_t)e * DMODEL * HID;   // [D, H] row-major
    int tid  = threadIdx.x;
    int arow = tid >> 1, ah = (tid & 1) * 4;          // 2 threads per A row (float4 each)
    int gm_load = m0 + arow;
    const float* aptr = nullptr;
    if (gm_load < n_e) {
        int token = g_assign[e * T_TOK + gm_load] >> 1;
        aptr = x + (size_t)token * DMODEL + ah;
    }
    int brow = tid >> 5, bcol = (tid & 31) * 4;
    const float* bptr = B + (size_t)brow * HID + n0 + bcol;

    float acc[8][8];
#pragma unroll
    for (int i = 0; i < 8; i++)
#pragma unroll
        for (int j = 0; j < 8; j++) acc[i][j] = 0.f;

    int tx = tid & 15, ty = tid >> 4;

    for (int bk = 0; bk < DMODEL; bk += 8) {
        float4 av = aptr ? *(const float4*)(aptr + bk) : make_float4(0.f, 0.f, 0.f, 0.f);
        As[ah + 0][arow] = av.x; As[ah + 1][arow] = av.y;
        As[ah + 2][arow] = av.z; As[ah + 3][arow] = av.w;
        float4 bv = *(const float4*)(bptr + (size_t)bk * HID);
        *(float4*)&Bs[brow][bcol] = bv;
        __syncthreads();
#pragma unroll
        for (int kk = 0; kk < 8; kk++) {
            float a[8], b[8];
            *(float4*)&a[0] = *(const float4*)&As[kk][ty * 8];
            *(float4*)&a[4] = *(const float4*)&As[kk][ty * 8 + 4];
            *(float4*)&b[0] = *(const float4*)&Bs[kk][tx * 8];
            *(float4*)&b[4] = *(const float4*)&Bs[kk][tx * 8 + 4];
#pragma unroll
            for (int i = 0; i < 8; i++)
#pragma unroll
                for (int j = 0; j < 8; j++) acc[i][j] += a[i] * b[j];
        }
        __syncthreads();
    }

    float* Hout = g_hidden + (size_t)e * T_TOK * HID;
#pragma unroll
    for (int i = 0; i < 8; i++) {
        int m = m0 + ty * 8 + i;
        if (m >= n_e) break;
#pragma unroll
        for (int j = 0; j < 8; j++) {
            int n = n0 + tx * 8 + j;
            float v = acc[i][j] + b1[e * HID + n];
            Hout[(size_t)m * HID + n] = gelu_tanh(v);
        }
    }
}

// ---- FFN GEMM 2: y = gate_w * (hidden @ W2[e] + b2[e]) -> g_ys[assignment] ----
__global__ __launch_bounds__(256, 2)
void ffn2_kernel(const float* __restrict__ W2, const float* __restrict__ b2) {
    int e = blockIdx.z;
    int n_e = g_count[e];
    int m0 = blockIdx.y * 128;
    if (m0 >= n_e) return;
    int n0 = blockIdx.x * 128;

    __shared__ float As[8][128];
    __shared__ float Bs[8][128];

    const float* A = g_hidden + (size_t)e * T_TOK * HID;      // [rows, H]
    const float* B = W2 + (size_t)e * HID * DMODEL;           // [H, D]
    int tid  = threadIdx.x;
    int arow = tid >> 1, ah = (tid & 1) * 4;
    int gm_load = m0 + arow;
    int gm_safe = gm_load < T_TOK ? gm_load : (T_TOK - 1);    // stale rows unused; stay in-bounds
    const float* aptr = A + (size_t)gm_safe * HID + ah;
    int brow = tid >> 5, bcol = (tid & 31) * 4;
    const float* bptr = B + (size_t)brow * DMODEL + n0 + bcol;

    float acc[8][8];
#pragma unroll
    for (int i = 0; i < 8; i++)
#pragma unroll
        for (int j = 0; j < 8; j++) acc[i][j] = 0.f;

    int tx = tid & 15, ty = tid >> 4;

    for (int bk = 0; bk < HID; bk += 8) {
        float4 av = *(const float4*)(aptr + bk);
        As[ah + 0][arow] = av.x; As[ah + 1][arow] = av.y;
        As[ah + 2][arow] = av.z; As[ah + 3][arow] = av.w;
        float4 bv = *(const float4*)(bptr + (size_t)bk * DMODEL);
        *(float4*)&Bs[brow][bcol] = bv;
        __syncthreads();
#pragma unroll
        for (int kk = 0; kk < 8; kk++) {
            float a[8], b[8];
            *(float4*)&a[0] = *(const float4*)&As[kk][ty * 8];
            *(float4*)&a[4] = *(const float4*)&As[kk][ty * 8 + 4];
            *(float4*)&b[0] = *(const float4*)&Bs[kk][tx * 8];
            *(float4*)&b[4] = *(const float4*)&Bs[kk][tx * 8 + 4];
#pragma unroll
            for (int i = 0; i < 8; i++)
#pragma unroll
                for (int j = 0; j < 8; j++) acc[i][j] += a[i] * b[j];
        }
        __syncthreads();
    }

#pragma unroll
    for (int i = 0; i < 8; i++) {
        int m = m0 + ty * 8 + i;
        if (m >= n_e) break;
        int assign = g_assign[e * T_TOK + m];
        float w = g_gatew[assign];
        float* yrow = g_ys + (size_t)assign * DMODEL;
#pragma unroll
        for (int j = 0; j < 8; j++) {
            int n = n0 + tx * 8 + j;
            yrow[n] = w * (acc[i][j] + b2[e * DMODEL + n]);
        }
    }
}

// ---- Combine: out[t] = ys[2t] + ys[2t+1] (softmax weights sum to 1, so b2 contributes once) ----
__global__ void combine_kernel(float* __restrict__ out) {
    int i4 = blockIdx.x * blockDim.x + threadIdx.x;    // over T*D/4
    int t  = i4 >> 8;                                  // D/4 = 256 float4 per token
    int d4 = i4 & 255;
    const float4 a = ((const float4*)(g_ys + (size_t)(2 * t) * DMODEL))[d4];
    const float4 b = ((const float4*)(g_ys + (size_t)(2 * t + 1) * DMODEL))[d4];
    float4 r; r.x = a.x + b.x; r.y = a.y + b.y; r.z = a.z + b.z; r.w = a.w + b.w;
    ((float4*)(out + (size_t)t * DMODEL))[d4] = r;
}

extern "C" void kernel_launch(void* const* d_in, const int* in_sizes, int n_in,
                              void* d_out, int out_size) {
    const float* x  = (const float*)d_in[0];
    const float* Wg = (const float*)d_in[1];
    const float* bg = (const float*)d_in[2];
    const float* W1 = (const float*)d_in[3];
    const float* b1 = (const float*)d_in[4];
    const float* W2 = (const float*)d_in[5];
    const float* b2 = (const float*)d_in[6];
    float* out = (float*)d_out;

    int write_idx = (out_size >= T_TOK * DMODEL + 2 * T_TOK) ? 1 : 0;

    zero_counts_kernel<<<1, 32>>>();
    gate_kernel<<<T_TOK / 8, 256>>>(x, Wg, bg, out + (size_t)T_TOK * DMODEL, write_idx);
    ffn1_kernel<<<dim3(HID / 128, T_TOK / 128, NEXP), 256>>>(x, W1, b1);
    ffn2_kernel<<<dim3(DMODEL / 128, T_TOK / 128, NEXP), 256>>>(W2, b2);
    combine_kernel<<<(T_TOK * DMODEL / 4) / 256, 256>>>(out);
}

// round 2
// speedup vs baseline: 3.0865x; 3.0865x over previous
#include <cuda_runtime.h>
#include <math.h>
#include <stdint.h>

// Problem constants: E=8 experts, D=1024, H=2048, T=2048, top_k=2
#define T_TOK  2048
#define DMODEL 1024
#define HID    2048
#define NEXP   8

// ---- Scratch (device globals: allocation-free) ----
__device__ float g_hidden[(size_t)NEXP * T_TOK * HID];   // per-expert gelu(h) rows
__device__ float g_ys[(size_t)T_TOK * 2 * DMODEL];       // per-assignment weighted output
__device__ float g_gatew[T_TOK * 2];                     // softmaxed gate weight per assignment
__device__ int   g_assign[NEXP * T_TOK];                 // per-expert assignment ids (token*2+slot)
__device__ int   g_count[NEXP];

__global__ void zero_counts_kernel() {
    if (threadIdx.x < NEXP) g_count[threadIdx.x] = 0;
}

// ---- Gate: exact fp32 logits, top-2, softmax. One warp per token. ----
__global__ void gate_kernel(const float* __restrict__ x, const float* __restrict__ Wg,
                            const float* __restrict__ bg, float* __restrict__ out_tail,
                            int write_idx) {
    int warp = (blockIdx.x * blockDim.x + threadIdx.x) >> 5;
    int lane = threadIdx.x & 31;
    if (warp >= T_TOK) return;
    const float* xr = x + (size_t)warp * DMODEL;
    float acc[NEXP];
#pragma unroll
    for (int e = 0; e < NEXP; e++) acc[e] = 0.f;
    for (int k = lane; k < DMODEL; k += 32) {
        float xv = xr[k];
        const float* wr = Wg + k * NEXP;
#pragma unroll
        for (int e = 0; e < NEXP; e++) acc[e] += xv * wr[e];
    }
#pragma unroll
    for (int e = 0; e < NEXP; e++) {
#pragma unroll
        for (int off = 16; off > 0; off >>= 1)
            acc[e] += __shfl_down_sync(0xffffffffu, acc[e], off);
    }
    if (lane == 0) {
#pragma unroll
        for (int e = 0; e < NEXP; e++) acc[e] += bg[e];
        int i0 = 0; float v0 = acc[0];
#pragma unroll
        for (int e = 1; e < NEXP; e++) if (acc[e] > v0) { v0 = acc[e]; i0 = e; }
        int i1 = -1; float v1 = -INFINITY;
#pragma unroll
        for (int e = 0; e < NEXP; e++) if (e != i0 && acc[e] > v1) { v1 = acc[e]; i1 = e; }
        float ex = expf(v1 - v0);
        float inv = 1.f / (1.f + ex);
        g_gatew[2 * warp]     = inv;
        g_gatew[2 * warp + 1] = ex * inv;
        int p0 = atomicAdd(&g_count[i0], 1);
        g_assign[i0 * T_TOK + p0] = 2 * warp;
        int p1 = atomicAdd(&g_count[i1], 1);
        g_assign[i1 * T_TOK + p1] = 2 * warp + 1;
        if (write_idx) {
            out_tail[2 * warp]     = (float)i0;
            out_tail[2 * warp + 1] = (float)i1;
        }
    }
}

// ---- tf32 MMA helpers ----
__device__ __forceinline__ uint32_t f2tf32(float x) {
    uint32_t u; asm("cvt.rna.tf32.f32 %0, %1;" : "=r"(u) : "f"(x)); return u;
}
__device__ __forceinline__ void mma_tf32(float* d, const uint32_t* a, const uint32_t* b) {
    asm volatile(
        "mma.sync.aligned.m16n8k8.row.col.f32.tf32.tf32.f32 "
        "{%0,%1,%2,%3}, {%4,%5,%6,%7}, {%8,%9}, {%0,%1,%2,%3};\n"
        : "+f"(d[0]), "+f"(d[1]), "+f"(d[2]), "+f"(d[3])
        : "r"(a[0]), "r"(a[1]), "r"(a[2]), "r"(a[3]), "r"(b[0]), "r"(b[1]));
}
__device__ __forceinline__ void cpa16(uint32_t dst, const void* src) {
    asm volatile("cp.async.cg.shared.global [%0], [%1], 16;\n" :: "r"(dst), "l"(src));
}
// gelu(tanh-approx): 0.5*v*(1+tanh(a)) == v * sigmoid(2a), one MUFU exp
__device__ __forceinline__ float fast_gelu(float v) {
    float a2 = -1.5957691216057308f * (v + 0.044715f * v * v * v);
    return v / (1.f + __expf(a2));
}

// SMEM layout (floats): A[2][128][36] | B[2][32][132] | s_src[128] | s_asn[128]
#define SA_BUF  (128 * 36)
#define SB_BUF  (32 * 132)
#define SB_OFF  (2 * SA_BUF)
#define SRC_OFF (SB_OFF + 2 * SB_BUF)
#define ASN_OFF (SRC_OFF + 128)
#define SMEM_FLOATS (ASN_OFF + 128)
#define SMEM_BYTES  (SMEM_FLOATS * 4)

// ---- FFN1: hidden = gelu(gather(x) @ W1[e] + b1[e]), tf32 tensor cores ----
__global__ __launch_bounds__(256, 2)
void ffn1_kernel(const float* __restrict__ x, const float* __restrict__ W1,
                 const float* __restrict__ b1) {
    extern __shared__ float smem[];
    const int e   = blockIdx.z;
    const int n_e = g_count[e];
    const int m0  = blockIdx.y * 128;
    if (m0 >= n_e) return;
    const int n0  = blockIdx.x * 128;

    const int tid  = threadIdx.x;
    const int wid  = tid >> 5, lane = tid & 31;
    const int gid  = lane >> 2, tig = lane & 3;
    const int wmb  = (wid & 1) * 64;   // warp M offset
    const int wnb  = (wid >> 1) * 32;  // warp N offset

    float*  sA    = smem;
    float*  sB    = smem + SB_OFF;
    int*    s_src = (int*)(smem + SRC_OFF);
    const uint32_t smem_u32 = (uint32_t)__cvta_generic_to_shared(smem);

    // token index per tile row (clamped; extra rows masked in epilogue)
    if (tid < 128) {
        int gm = m0 + tid;
        int cl = gm < n_e ? gm : (n_e - 1);
        s_src[tid] = g_assign[e * T_TOK + cl] >> 1;
    }
    __syncthreads();

    const float* Wb = W1 + (size_t)e * DMODEL * HID;  // [D,H]

    float acc[4][4][4];
#pragma unroll
    for (int i = 0; i < 4; i++)
#pragma unroll
        for (int j = 0; j < 4; j++)
#pragma unroll
            for (int v = 0; v < 4; v++) acc[i][j][v] = 0.f;

#define LOAD_TILE1(KT, BUF) do {                                               \
    int k0 = (KT) * 32;                                                        \
    _Pragma("unroll")                                                          \
    for (int i = 0; i < 4; i++) {                                              \
        int f = tid + i * 256; int row = f >> 3, kq = f & 7;                   \
        const float* src = x + (size_t)s_src[row] * DMODEL + k0 + kq * 4;      \
        cpa16(smem_u32 + ((BUF) * SA_BUF + row * 36 + kq * 4) * 4, src);       \
    }                                                                          \
    _Pragma("unroll")                                                          \
    for (int i = 0; i < 4; i++) {                                              \
        int f = tid + i * 256; int cq = f & 31, k = f >> 5;                    \
        const float* src = Wb + (size_t)(k0 + k) * HID + n0 + cq * 4;          \
        cpa16(smem_u32 + (SB_OFF + (BUF) * SB_BUF + k * 132 + cq * 4) * 4, src); \
    }                                                                          \
    asm volatile("cp.async.commit_group;\n"); } while (0)

    const int NT = DMODEL / 32;
    LOAD_TILE1(0, 0);
    for (int kt = 0; kt < NT; kt++) {
        int buf = kt & 1;
        if (kt + 1 < NT) {
            LOAD_TILE1(kt + 1, buf ^ 1);
            asm volatile("cp.async.wait_group 1;\n");
        } else {
            asm volatile("cp.async.wait_group 0;\n");
        }
        __syncthreads();
        const float* As = sA + buf * SA_BUF;
        const float* Bs = sB + buf * SB_BUF;
#pragma unroll
        for (int ks = 0; ks < 4; ks++) {
            int kk = ks * 8;
            uint32_t bf[4][2], af[4][4];
#pragma unroll
            for (int nf = 0; nf < 4; nf++) {
                int c = wnb + nf * 8 + gid;
                bf[nf][0] = f2tf32(Bs[(kk + tig) * 132 + c]);
                bf[nf][1] = f2tf32(Bs[(kk + tig + 4) * 132 + c]);
            }
#pragma unroll
            for (int mf = 0; mf < 4; mf++) {
                int r = wmb + mf * 16 + gid;
                af[mf][0] = f2tf32(As[r * 36 + kk + tig]);
                af[mf][1] = f2tf32(As[(r + 8) * 36 + kk + tig]);
                af[mf][2] = f2tf32(As[r * 36 + kk + tig + 4]);
                af[mf][3] = f2tf32(As[(r + 8) * 36 + kk + tig + 4]);
            }
#pragma unroll
            for (int mf = 0; mf < 4; mf++)
#pragma unroll
                for (int nf = 0; nf < 4; nf++)
                    mma_tf32(acc[mf][nf], af[mf], bf[nf]);
        }
        __syncthreads();
    }
#undef LOAD_TILE1

    float* Hout = g_hidden + (size_t)e * T_TOK * HID;
    const float* b1e = b1 + e * HID;
#pragma unroll
    for (int mf = 0; mf < 4; mf++) {
#pragma unroll
        for (int half = 0; half < 2; half++) {
            int r = m0 + wmb + mf * 16 + gid + 8 * half;
            if (r < n_e) {
                float* orow = Hout + (size_t)r * HID;
#pragma unroll
                for (int nf = 0; nf < 4; nf++) {
                    int c = n0 + wnb + nf * 8 + tig * 2;
                    float v0 = acc[mf][nf][half * 2 + 0] + b1e[c];
                    float v1 = acc[mf][nf][half * 2 + 1] + b1e[c + 1];
                    float2 w = make_float2(fast_gelu(v0), fast_gelu(v1));
                    *(float2*)(orow + c) = w;
                }
            }
        }
    }
}

// ---- FFN2: y = gate_w * (hidden @ W2[e] + b2[e]) -> g_ys[assignment] ----
__global__ __launch_bounds__(256, 2)
void ffn2_kernel(const float* __restrict__ W2, const float* __restrict__ b2) {
    extern __shared__ float smem[];
    const int e   = blockIdx.z;
    const int n_e = g_count[e];
    const int m0  = blockIdx.y * 128;
    if (m0 >= n_e) return;
    const int n0  = blockIdx.x * 128;

    const int tid  = threadIdx.x;
    const int wid  = tid >> 5, lane = tid & 31;
    const int gid  = lane >> 2, tig = lane & 3;
    const int wmb  = (wid & 1) * 64;
    const int wnb  = (wid >> 1) * 32;

    float*  sA    = smem;
    float*  sB    = smem + SB_OFF;
    int*    s_src = (int*)(smem + SRC_OFF);
    int*    s_asn = (int*)(smem + ASN_OFF);
    const uint32_t smem_u32 = (uint32_t)__cvta_generic_to_shared(smem);

    if (tid < 128) {
        int gm = m0 + tid;
        int cl = gm < n_e ? gm : (n_e - 1);
        s_src[tid] = cl;                             // hidden row
        s_asn[tid] = g_assign[e * T_TOK + cl];       // assignment id for epilogue
    }
    __syncthreads();

    const float* Ab = g_hidden + (size_t)e * T_TOK * HID;  // [rows,H]
    const float* Wb = W2 + (size_t)e * HID * DMODEL;       // [H,D]

    float acc[4][4][4];
#pragma unroll
    for (int i = 0; i < 4; i++)
#pragma unroll
        for (int j = 0; j < 4; j++)
#pragma unroll
            for (int v = 0; v < 4; v++) acc[i][j][v] = 0.f;

#define LOAD_TILE2(KT, BUF) do {                                               \
    int k0 = (KT) * 32;                                                        \
    _Pragma("unroll")                                                          \
    for (int i = 0; i < 4; i++) {                                              \
        int f = tid + i * 256; int row = f >> 3, kq = f & 7;                   \
        const float* src = Ab + (size_t)s_src[row] * HID + k0 + kq * 4;        \
        cpa16(smem_u32 + ((BUF) * SA_BUF + row * 36 + kq * 4) * 4, src);       \
    }                                                                          \
    _Pragma("unroll")                                                          \
    for (int i = 0; i < 4; i++) {                                              \
        int f = tid + i * 256; int cq = f & 31, k = f >> 5;                    \
        const float* src = Wb + (size_t)(k0 + k) * DMODEL + n0 + cq * 4;       \
        cpa16(smem_u32 + (SB_OFF + (BUF) * SB_BUF + k * 132 + cq * 4) * 4, src); \
    }                                                                          \
    asm volatile("cp.async.commit_group;\n"); } while (0)

    const int NT = HID / 32;
    LOAD_TILE2(0, 0);
    for (int kt = 0; kt < NT; kt++) {
        int buf = kt & 1;
        if (kt + 1 < NT) {
            LOAD_TILE2(kt + 1, buf ^ 1);
            asm volatile("cp.async.wait_group 1;\n");
        } else {
            asm volatile("cp.async.wait_group 0;\n");
        }
        __syncthreads();
        const float* As = sA + buf * SA_BUF;
        const float* Bs = sB + buf * SB_BUF;
#pragma unroll
        for (int ks = 0; ks < 4; ks++) {
            int kk = ks * 8;
            uint32_t bf[4][2], af[4][4];
#pragma unroll
            for (int nf = 0; nf < 4; nf++) {
                int c = wnb + nf * 8 + gid;
                bf[nf][0] = f2tf32(Bs[(kk + tig) * 132 + c]);
                bf[nf][1] = f2tf32(Bs[(kk + tig + 4) * 132 + c]);
            }
#pragma unroll
            for (int mf = 0; mf < 4; mf++) {
                int r = wmb + mf * 16 + gid;
                af[mf][0] = f2tf32(As[r * 36 + kk + tig]);
                af[mf][1] = f2tf32(As[(r + 8) * 36 + kk + tig]);
                af[mf][2] = f2tf32(As[r * 36 + kk + tig + 4]);
                af[mf][3] = f2tf32(As[(r + 8) * 36 + kk + tig + 4]);
            }
#pragma unroll
            for (int mf = 0; mf < 4; mf++)
#pragma unroll
                for (int nf = 0; nf < 4; nf++)
                    mma_tf32(acc[mf][nf], af[mf], bf[nf]);
        }
        __syncthreads();
    }
#undef LOAD_TILE2

    const float* b2e = b2 + e * DMODEL;
#pragma unroll
    for (int mf = 0; mf < 4; mf++) {
#pragma unroll
        for (int half = 0; half < 2; half++) {
            int lr = wmb + mf * 16 + gid + 8 * half;
            int r  = m0 + lr;
            if (r < n_e) {
                int asn  = s_asn[lr];
                float w  = g_gatew[asn];
                float* yrow = g_ys + (size_t)asn * DMODEL;
#pragma unroll
                for (int nf = 0; nf < 4; nf++) {
                    int c = n0 + wnb + nf * 8 + tig * 2;
                    float v0 = w * (acc[mf][nf][half * 2 + 0] + b2e[c]);
                    float v1 = w * (acc[mf][nf][half * 2 + 1] + b2e[c + 1]);
                    *(float2*)(yrow + c) = make_float2(v0, v1);
                }
            }
        }
    }
}

// ---- Combine: out[t] = ys[2t] + ys[2t+1] ----
__global__ void combine_kernel(float* __restrict__ out) {
    int i4 = blockIdx.x * blockDim.x + threadIdx.x;
    int t  = i4 >> 8;
    int d4 = i4 & 255;
    const float4 a = ((const float4*)(g_ys + (size_t)(2 * t) * DMODEL))[d4];
    const float4 b = ((const float4*)(g_ys + (size_t)(2 * t + 1) * DMODEL))[d4];
    float4 r; r.x = a.x + b.x; r.y = a.y + b.y; r.z = a.z + b.z; r.w = a.w + b.w;
    ((float4*)(out + (size_t)t * DMODEL))[d4] = r;
}

extern "C" void kernel_launch(void* const* d_in, const int* in_sizes, int n_in,
                              void* d_out, int out_size) {
    const float* x  = (const float*)d_in[0];
    const float* Wg = (const float*)d_in[1];
    const float* bg = (const float*)d_in[2];
    const float* W1 = (const float*)d_in[3];
    const float* b1 = (const float*)d_in[4];
    const float* W2 = (const float*)d_in[5];
    const float* b2 = (const float*)d_in[6];
    float* out = (float*)d_out;

    int write_idx = (out_size >= T_TOK * DMODEL + 2 * T_TOK) ? 1 : 0;

    cudaFuncSetAttribute(ffn1_kernel, cudaFuncAttributeMaxDynamicSharedMemorySize, SMEM_BYTES);
    cudaFuncSetAttribute(ffn2_kernel, cudaFuncAttributeMaxDynamicSharedMemorySize, SMEM_BYTES);

    zero_counts_kernel<<<1, 32>>>();
    gate_kernel<<<T_TOK / 8, 256>>>(x, Wg, bg, out + (size_t)T_TOK * DMODEL, write_idx);
    ffn1_kernel<<<dim3(HID / 128, T_TOK / 128, NEXP), 256, SMEM_BYTES>>>(x, W1, b1);
    ffn2_kernel<<<dim3(DMODEL / 128, T_TOK / 128, NEXP), 256, SMEM_BYTES>>>(W2, b2);
    combine_kernel<<<(T_TOK * DMODEL / 4) / 256, 256>>>(out);
}